// round 6
// baseline (speedup 1.0000x reference)
#include <cuda_runtime.h>
#include <cuda_bf16.h>
#include <cstdint>

#define TABLE_SCALE 1024.0f   // 2^10
#define TABLE_MAX   4095      // TABLE_SIZE - 1
#define UNROLL 4
#define THREADS 256
#define CHUNK_F4 (THREADS * UNROLL)          // 1024 float4 per CTA tile
#define CHUNK_BYTES (CHUNK_F4 * 16)          // 16 KB

__device__ __forceinline__ float secgelu_one(float x, const float* __restrict__ table) {
    float a = fabsf(x);
    int c = (int)(a * TABLE_SCALE);          // truncation toward zero, a >= 0
    c = min(c, TABLE_MAX);
    float relu_x = x >= 0.0f ? x : 0.0f;
    return relu_x - __ldg(table + c);
}

__device__ __forceinline__ float4 secgelu_vec4(float4 v, const float* __restrict__ table) {
    float4 r;
    r.x = secgelu_one(v.x, table);
    r.y = secgelu_one(v.y, table);
    r.z = secgelu_one(v.z, table);
    r.w = secgelu_one(v.w, table);
    return r;
}

// LSU-dispatch-relief variant: results staged in smem (STS ~4-5 cyc issue vs
// STG.128's 12) and written out with ONE cp.async.bulk (1D bulk TMA store)
// per 16 KB tile — near-zero dispatch cost. Streaming loads stay LDG.128 .cs
// front-batched (MLP_p1=4); table gathers stay __ldg (L1-resident 16 KB).
__global__ void __launch_bounds__(THREADS) SecGELU_kernel(
    const float4* __restrict__ x,
    const float* __restrict__ table,
    float4* __restrict__ out,
    int n4)
{
    __shared__ alignas(128) float4 stage[CHUNK_F4];   // 16 KB

    int base = blockIdx.x * CHUNK_F4 + threadIdx.x;

    if (base + (UNROLL - 1) * THREADS < n4) {
        float4 v[UNROLL];
        #pragma unroll
        for (int k = 0; k < UNROLL; k++)
            v[k] = __ldcs(x + base + k * THREADS);    // front-batched, independent

        #pragma unroll
        for (int k = 0; k < UNROLL; k++)
            stage[threadIdx.x + k * THREADS] = secgelu_vec4(v[k], table);

        __syncthreads();
        // Make generic-proxy smem writes visible to the async proxy.
        asm volatile("fence.proxy.async.shared::cta;" ::: "memory");

        if (threadIdx.x == 0) {
            uint32_t saddr;
            asm("{ .reg .u64 t; cvta.to.shared.u64 t, %1; cvt.u32.u64 %0, t; }"
                : "=r"(saddr) : "l"(stage));
            float4* gdst = out + (size_t)blockIdx.x * CHUNK_F4;
            asm volatile(
                "cp.async.bulk.global.shared::cta.bulk_group [%0], [%1], %2;"
                :: "l"(gdst), "r"(saddr), "n"(CHUNK_BYTES) : "memory");
            asm volatile("cp.async.bulk.commit_group;" ::: "memory");
            asm volatile("cp.async.bulk.wait_group 0;" ::: "memory");
        }
    } else {
        // Partial tile fallback (not hit for n4 = 2^24): plain STG path.
        #pragma unroll
        for (int k = 0; k < UNROLL; k++) {
            int i = base + k * THREADS;
            if (i < n4) {
                float4 t = __ldcs(x + i);
                __stcs(out + i, secgelu_vec4(t, table));
            }
        }
    }
}

// Tail handler for n not divisible by 4 (not needed for 2^26, but safe).
__global__ void SecGELU_tail(
    const float* __restrict__ x,
    const float* __restrict__ table,
    float* __restrict__ out,
    int start, int n)
{
    int i = start + blockIdx.x * blockDim.x + threadIdx.x;
    if (i >= n) return;
    out[i] = secgelu_one(x[i], table);
}

extern "C" void kernel_launch(void* const* d_in, const int* in_sizes, int n_in,
                              void* d_out, int out_size) {
    const float* x     = (const float*)d_in[0];
    const float* table = (const float*)d_in[1];
    float* out = (float*)d_out;

    int n  = in_sizes[0];
    int n4 = n >> 2;

    if (n4 > 0) {
        int blocks = (n4 + CHUNK_F4 - 1) / CHUNK_F4;
        SecGELU_kernel<<<blocks, THREADS>>>(
            (const float4*)x, table, (float4*)out, n4);
    }
    int rem = n - (n4 << 2);
    if (rem > 0) {
        SecGELU_tail<<<1, 32>>>(x, table, out, n4 << 2, n);
    }
}

// round 7
// speedup vs baseline: 1.6596x; 1.6596x over previous
#include <cuda_runtime.h>
#include <cuda_bf16.h>

#define TABLE_SCALE 1024.0f   // 2^10
#define TABLE_MAX   4095      // TABLE_SIZE - 1
#define UNROLL 4
#define THREADS 512

__device__ __forceinline__ float secgelu_one(float x, const float* __restrict__ table) {
    float a = fabsf(x);
    int c = (int)(a * TABLE_SCALE);          // truncation toward zero, a >= 0
    c = min(c, TABLE_MAX);
    float relu_x = x >= 0.0f ? x : 0.0f;
    return relu_x - __ldg(table + c);
}

__device__ __forceinline__ float4 secgelu_vec4(float4 v, const float* __restrict__ table) {
    float4 r;
    r.x = secgelu_one(v.x, table);
    r.y = secgelu_one(v.y, table);
    r.z = secgelu_one(v.z, table);
    r.w = secgelu_one(v.w, table);
    return r;
}

// Best-known shape (R2): flat grid, 4 front-batched independent LDG.128s per
// thread (MLP_p1=4 hides DRAM latency), .cs streaming hints keep the 512 MiB
// x/out streams from thrashing L2 while the 16 KB table stays L1-resident
// via __ldg. THREADS=512 halves CTA count at identical coalescing/occupancy.
__global__ void __launch_bounds__(THREADS) SecGELU_kernel(
    const float4* __restrict__ x,
    const float* __restrict__ table,
    float4* __restrict__ out,
    int n4)
{
    int base = blockIdx.x * (THREADS * UNROLL) + threadIdx.x;

    if (base + (UNROLL - 1) * THREADS < n4) {
        float4 v[UNROLL];
        #pragma unroll
        for (int k = 0; k < UNROLL; k++)
            v[k] = __ldcs(x + base + k * THREADS);   // front-batched, independent

        #pragma unroll
        for (int k = 0; k < UNROLL; k++)
            __stcs(out + base + k * THREADS, secgelu_vec4(v[k], table));
    } else {
        #pragma unroll
        for (int k = 0; k < UNROLL; k++) {
            int i = base + k * THREADS;
            if (i < n4) {
                float4 t = __ldcs(x + i);
                __stcs(out + i, secgelu_vec4(t, table));
            }
        }
    }
}

// Tail handler for n not divisible by 4 (not needed for 2^26, but safe).
__global__ void SecGELU_tail(
    const float* __restrict__ x,
    const float* __restrict__ table,
    float* __restrict__ out,
    int start, int n)
{
    int i = start + blockIdx.x * blockDim.x + threadIdx.x;
    if (i >= n) return;
    out[i] = secgelu_one(x[i], table);
}

extern "C" void kernel_launch(void* const* d_in, const int* in_sizes, int n_in,
                              void* d_out, int out_size) {
    const float* x     = (const float*)d_in[0];
    const float* table = (const float*)d_in[1];
    float* out = (float*)d_out;

    int n  = in_sizes[0];
    int n4 = n >> 2;

    if (n4 > 0) {
        int per_block = THREADS * UNROLL;
        int blocks = (n4 + per_block - 1) / per_block;
        SecGELU_kernel<<<blocks, THREADS>>>(
            (const float4*)x, table, (float4*)out, n4);
    }
    int rem = n - (n4 << 2);
    if (rem > 0) {
        SecGELU_tail<<<1, 32>>>(x, table, out, n4 << 2, n);
    }
}

// round 8
// speedup vs baseline: 1.6691x; 1.0057x over previous
#include <cuda_runtime.h>
#include <cuda_bf16.h>

#define TABLE_SCALE 1024.0f   // 2^10
#define TABLE_MAX   4095      // TABLE_SIZE - 1
#define UNROLL 4
#define THREADS 256

__device__ __forceinline__ float secgelu_one(float x, const float* __restrict__ table) {
    float a = fabsf(x);
    int c = (int)(a * TABLE_SCALE);          // truncation toward zero, a >= 0
    c = min(c, TABLE_MAX);
    float relu_x = x >= 0.0f ? x : 0.0f;
    return relu_x - __ldg(table + c);
}

__device__ __forceinline__ float4 secgelu_vec4(float4 v, const float* __restrict__ table) {
    float4 r;
    r.x = secgelu_one(v.x, table);
    r.y = secgelu_one(v.y, table);
    r.z = secgelu_one(v.z, table);
    r.w = secgelu_one(v.w, table);
    return r;
}

// Best-known shape (R2): flat grid, U=4 front-batched independent LDG.128s
// per thread (MLP_p1=4), 256 threads, 16384 CTAs. Loads use .lu (last-use):
// read lines are dead after one use, so releasing them immediately frees L2
// capacity for the write stream to form longer bursts, reducing HBM R/W
// turnaround losses. Stores stay .cs streaming. The 16 KB table remains
// L1/L2-resident via plain __ldg.
__global__ void __launch_bounds__(THREADS) SecGELU_kernel(
    const float4* __restrict__ x,
    const float* __restrict__ table,
    float4* __restrict__ out,
    int n4)
{
    int base = blockIdx.x * (THREADS * UNROLL) + threadIdx.x;

    if (base + (UNROLL - 1) * THREADS < n4) {
        float4 v[UNROLL];
        #pragma unroll
        for (int k = 0; k < UNROLL; k++)
            v[k] = __ldlu(x + base + k * THREADS);   // front-batched, last-use

        #pragma unroll
        for (int k = 0; k < UNROLL; k++)
            __stcs(out + base + k * THREADS, secgelu_vec4(v[k], table));
    } else {
        #pragma unroll
        for (int k = 0; k < UNROLL; k++) {
            int i = base + k * THREADS;
            if (i < n4) {
                float4 t = __ldlu(x + i);
                __stcs(out + i, secgelu_vec4(t, table));
            }
        }
    }
}

// Tail handler for n not divisible by 4 (not needed for 2^26, but safe).
__global__ void SecGELU_tail(
    const float* __restrict__ x,
    const float* __restrict__ table,
    float* __restrict__ out,
    int start, int n)
{
    int i = start + blockIdx.x * blockDim.x + threadIdx.x;
    if (i >= n) return;
    out[i] = secgelu_one(x[i], table);
}

extern "C" void kernel_launch(void* const* d_in, const int* in_sizes, int n_in,
                              void* d_out, int out_size) {
    const float* x     = (const float*)d_in[0];
    const float* table = (const float*)d_in[1];
    float* out = (float*)d_out;

    int n  = in_sizes[0];
    int n4 = n >> 2;

    if (n4 > 0) {
        int per_block = THREADS * UNROLL;
        int blocks = (n4 + per_block - 1) / per_block;
        SecGELU_kernel<<<blocks, THREADS>>>(
            (const float4*)x, table, (float4*)out, n4);
    }
    int rem = n - (n4 << 2);
    if (rem > 0) {
        SecGELU_tail<<<1, 32>>>(x, table, out, n4 << 2, n);
    }
}

// round 9
// speedup vs baseline: 1.6995x; 1.0182x over previous
#include <cuda_runtime.h>
#include <cuda_bf16.h>

#define TABLE_SCALE 1024.0f   // 2^10
#define TABLE_SIZE  4096
#define TABLE_MAX   (TABLE_SIZE - 1)
#define UNROLL 4
#define THREADS 256

__device__ __forceinline__ int table_idx(float x) {
    int c = (int)(fabsf(x) * TABLE_SCALE);   // truncation toward zero
    return min(c, TABLE_MAX);
}

// R2 shape (flat grid, U=4 front-batched streaming loads, .cs hints) with
// table gathers moved to shared memory. LDS random gathers cost ~4 crossbar
// cycles (bank-conflict degree) vs ~30 L1tex sector-replay wavefronts per
// gather LDG — this unloads the L1tex queue that the streaming LDG/STG
// wavefronts share, letting DRAM injection run closer to peak. Table fill
// (16 KB per CTA) reads L2-resident data: no extra DRAM traffic.
__global__ void __launch_bounds__(THREADS) SecGELU_kernel(
    const float4* __restrict__ x,
    const float* __restrict__ table,
    float4* __restrict__ out,
    int n4)
{
    __shared__ float table_s[TABLE_SIZE];

    {   // cooperative fill: 4096 floats = 1024 float4, 4 per thread
        const float4* t4 = (const float4*)table;
        float4* s4 = (float4*)table_s;
        #pragma unroll
        for (int k = 0; k < TABLE_SIZE / 4 / THREADS; k++)
            s4[threadIdx.x + k * THREADS] = t4[threadIdx.x + k * THREADS];
    }
    __syncthreads();

    int base = blockIdx.x * (THREADS * UNROLL) + threadIdx.x;

    if (base + (UNROLL - 1) * THREADS < n4) {
        float4 v[UNROLL];
        #pragma unroll
        for (int k = 0; k < UNROLL; k++)
            v[k] = __ldcs(x + base + k * THREADS);   // front-batched, independent

        float t[UNROLL][4];
        #pragma unroll
        for (int k = 0; k < UNROLL; k++) {
            t[k][0] = table_s[table_idx(v[k].x)];
            t[k][1] = table_s[table_idx(v[k].y)];
            t[k][2] = table_s[table_idx(v[k].z)];
            t[k][3] = table_s[table_idx(v[k].w)];
        }

        #pragma unroll
        for (int k = 0; k < UNROLL; k++) {
            float4 r;
            r.x = (v[k].x >= 0.0f ? v[k].x : 0.0f) - t[k][0];
            r.y = (v[k].y >= 0.0f ? v[k].y : 0.0f) - t[k][1];
            r.z = (v[k].z >= 0.0f ? v[k].z : 0.0f) - t[k][2];
            r.w = (v[k].w >= 0.0f ? v[k].w : 0.0f) - t[k][3];
            __stcs(out + base + k * THREADS, r);
        }
    } else {
        #pragma unroll
        for (int k = 0; k < UNROLL; k++) {
            int i = base + k * THREADS;
            if (i < n4) {
                float4 v = __ldcs(x + i);
                float4 r;
                r.x = (v.x >= 0.0f ? v.x : 0.0f) - table_s[table_idx(v.x)];
                r.y = (v.y >= 0.0f ? v.y : 0.0f) - table_s[table_idx(v.y)];
                r.z = (v.z >= 0.0f ? v.z : 0.0f) - table_s[table_idx(v.z)];
                r.w = (v.w >= 0.0f ? v.w : 0.0f) - table_s[table_idx(v.w)];
                __stcs(out + i, r);
            }
        }
    }
}

// Tail handler for n not divisible by 4 (not needed for 2^26, but safe).
__global__ void SecGELU_tail(
    const float* __restrict__ x,
    const float* __restrict__ table,
    float* __restrict__ out,
    int start, int n)
{
    int i = start + blockIdx.x * blockDim.x + threadIdx.x;
    if (i >= n) return;
    float v = x[i];
    out[i] = (v >= 0.0f ? v : 0.0f) - __ldg(table + table_idx(v));
}

extern "C" void kernel_launch(void* const* d_in, const int* in_sizes, int n_in,
                              void* d_out, int out_size) {
    const float* x     = (const float*)d_in[0];
    const float* table = (const float*)d_in[1];
    float* out = (float*)d_out;

    int n  = in_sizes[0];
    int n4 = n >> 2;

    if (n4 > 0) {
        int per_block = THREADS * UNROLL;
        int blocks = (n4 + per_block - 1) / per_block;
        SecGELU_kernel<<<blocks, THREADS>>>(
            (const float4*)x, table, (float4*)out, n4);
    }
    int rem = n - (n4 << 2);
    if (rem > 0) {
        SecGELU_tail<<<1, 32>>>(x, table, out, n4 << 2, n);
    }
}